// round 8
// baseline (speedup 1.0000x reference)
#include <cuda_runtime.h>
#include <cuda_fp16.h>
#include <math.h>
#include <stdint.h>

// ---------------- problem constants ----------------
#define E_        8
#define NTOK      8192
#define D_        1024
#define F_        2816
#define NSLOT     (NTOK * 2)
#define SLOT_PAD  (NSLOT + E_ * 128)   // 17408
#define OUT_ELEMS (NTOK * D_)

// mma tiling: CTA 128m x (64f | 128d), K=32 per stage, 2-stage reg double buffer
#define BK        32
#define ROWH      40                    // 32 data halves + 8 pad (80B rows)
#define TILEH     (128 * ROWH)          // halves per tile buffer

#define PROBE_ACT (128 * F_)
#define PROBE_Y2  (128 * D_)

// ---------------- static device scratch ----------------
__device__ __align__(128) __half g_xp[(size_t)SLOT_PAD * D_];
__device__ __align__(128) __half g_gt[(size_t)E_ * F_ * D_];   // gate^T (E,F,D)
__device__ __align__(128) __half g_ut[(size_t)E_ * F_ * D_];   // up^T   (E,F,D)
__device__ __align__(128) __half g_dt[(size_t)E_ * D_ * F_];   // down^T (E,D,F)
__device__ __align__(128) __half g_act[(size_t)SLOT_PAD * F_];
__device__ __align__(128) float  g_y2[(size_t)SLOT_PAD * D_];

__device__ int   g_perm_token[SLOT_PAD];
__device__ float g_perm_w[SLOT_PAD];
__device__ int   g_tok_slot[NSLOT];
__device__ int   g_counts[E_];
__device__ int   g_cursor[E_];
__device__ int   g_pad_off[E_ + 1];
__device__ int   g_topk_idx[NSLOT];
__device__ float g_topk_w[NSLOT];
__device__ int   g_flagA;
__device__ int   g_flagB;
__device__ int   g_useMMA;

// ---------------- mma ----------------
static __device__ __forceinline__ void mma_f16(float* d, const uint32_t* a, const uint32_t* b) {
    asm volatile("mma.sync.aligned.m16n8k16.row.col.f32.f16.f16.f32 "
                 "{%0,%1,%2,%3}, {%4,%5,%6,%7}, {%8,%9}, {%0,%1,%2,%3};"
                 : "+f"(d[0]), "+f"(d[1]), "+f"(d[2]), "+f"(d[3])
                 : "r"(a[0]), "r"(a[1]), "r"(a[2]), "r"(a[3]), "r"(b[0]), "r"(b[1]));
}

// ---------------- mma self-test: all-ones 16x16 @ 16x8 => all 16.0 --------
__global__ void mma_selftest() {
    if (threadIdx.x >= 32) return;
    uint32_t one2 = 0x3C003C00u;
    uint32_t a[4] = {one2, one2, one2, one2};
    uint32_t b[2] = {one2, one2};
    float d[4] = {0.f, 0.f, 0.f, 0.f};
    mma_f16(d, a, b);
    bool ok = (d[0] == 16.f) && (d[1] == 16.f) && (d[2] == 16.f) && (d[3] == 16.f);
    unsigned m = __ballot_sync(0xffffffffu, ok);
    if (threadIdx.x == 0) g_useMMA = (m == 0xffffffffu) ? 1 : 0;
}

// ---------------- init ----------------
__global__ void init_kernel() {
    int i = blockIdx.x * 256 + threadIdx.x;
    if (i < SLOT_PAD) { g_perm_token[i] = -1; g_perm_w[i] = 0.0f; }
    if (i < E_) g_counts[i] = 0;
    if (i == 0) { g_flagA = 0; g_flagB = 0; }
    if (i < PROBE_ACT) g_act[i] = __float2half(0.0f);
    if (i < PROBE_Y2)  g_y2[i] = 0.0f;
}

// ---------------- router / scan / fill (proven) ----------------
__global__ void router_kernel(const float* __restrict__ x, const float* __restrict__ rw) {
    int t = blockIdx.x;
    const float* xr = x + (size_t)t * D_;
    int lane = threadIdx.x & 31;
    int w    = threadIdx.x >> 5;

    double s = 0.0;
    for (int d = lane; d < D_; d += 32)
        s += (double)xr[d] * (double)rw[d * E_ + w];
    #pragma unroll
    for (int o = 16; o > 0; o >>= 1)
        s += __shfl_down_sync(0xffffffffu, s, o);

    __shared__ double sc[E_];
    if (lane == 0) sc[w] = s;
    __syncthreads();

    if (threadIdx.x == 0) {
        double m = sc[0];
        #pragma unroll
        for (int e = 1; e < E_; e++) m = fmax(m, sc[e]);
        double p[E_], sum = 0.0;
        #pragma unroll
        for (int e = 0; e < E_; e++) { p[e] = exp(sc[e] - m); sum += p[e]; }
        #pragma unroll
        for (int e = 0; e < E_; e++) p[e] /= sum;
        int i0 = 0;
        #pragma unroll
        for (int e = 1; e < E_; e++) if (p[e] > p[i0]) i0 = e;
        int i1 = (i0 == 0) ? 1 : 0;
        #pragma unroll
        for (int e = 0; e < E_; e++) { if (e == i0) continue; if (p[e] > p[i1]) i1 = e; }
        float p0 = (float)p[i0], p1 = (float)p[i1];
        float inv = 1.0f / (p0 + p1);
        g_topk_idx[t * 2 + 0] = i0;  g_topk_idx[t * 2 + 1] = i1;
        g_topk_w[t * 2 + 0] = p0 * inv;  g_topk_w[t * 2 + 1] = p1 * inv;
        atomicAdd(&g_counts[i0], 1);
        atomicAdd(&g_counts[i1], 1);
    }
}

__global__ void scan_kernel() {
    int off = 0;
    #pragma unroll
    for (int e = 0; e < E_; e++) {
        g_pad_off[e] = off;  g_cursor[e] = off;
        off += (g_counts[e] + 127) & ~127;
    }
    g_pad_off[E_] = off;
}

__global__ void fill_kernel() {
    int idx = blockIdx.x * blockDim.x + threadIdx.x;
    if (idx >= NSLOT) return;
    int e    = g_topk_idx[idx];
    int slot = atomicAdd(&g_cursor[e], 1);
    g_perm_token[slot] = idx >> 1;
    g_perm_w[slot]     = g_topk_w[idx];
    g_tok_slot[idx]    = slot;
}

// ---------------- prep (gated on g_useMMA) ----------------
__global__ void xgather_kernel(const float* __restrict__ x) {
    if (!g_useMMA) return;
    int slot = blockIdx.x;
    int tok  = g_perm_token[slot];
    size_t base = (size_t)slot * D_;
    for (int d = threadIdx.x; d < D_; d += blockDim.x) {
        float v = (tok >= 0) ? x[(size_t)tok * D_ + d] : 0.0f;
        g_xp[base + d] = __float2half(v);
    }
}

__global__ void tconv_kernel(const float* __restrict__ in,
                             __half* __restrict__ oh, int R, int C) {
    if (!g_useMMA) return;
    __shared__ float t[32][33];
    int e  = blockIdx.z;
    int c0 = blockIdx.x * 32, r0 = blockIdx.y * 32;
    const float* src = in + (size_t)e * R * C;
    #pragma unroll
    for (int i = 0; i < 4; i++) {
        int r = r0 + threadIdx.y + i * 8;
        t[threadIdx.y + i * 8][threadIdx.x] = src[(size_t)r * C + c0 + threadIdx.x];
    }
    __syncthreads();
    #pragma unroll
    for (int i = 0; i < 4; i++) {
        int c = c0 + threadIdx.y + i * 8;
        oh[(size_t)e * R * C + (size_t)c * R + r0 + threadIdx.x] =
            __float2half(t[threadIdx.x][threadIdx.y + i * 8]);
    }
}

// ---------------- per-stage compute: plain LDS fragments, K=32 ------------
static __device__ __forceinline__ void stage_mma(const __half* As, const __half* Bs,
                                                 int wm, int wn, int lane,
                                                 float acc[4][4][4]) {
    int lr = lane >> 2;          // 0..7
    int lk = (lane & 3) * 2;     // 0,2,4,6
    #pragma unroll
    for (int h = 0; h < 2; h++) {
        uint32_t a[4][4], b[4][2];
        #pragma unroll
        for (int i = 0; i < 4; i++) {
            const __half* ap = As + (size_t)(wm * 64 + 16 * i + lr) * ROWH + lk + 16 * h;
            a[i][0] = *(const uint32_t*)(ap);
            a[i][1] = *(const uint32_t*)(ap + 8 * ROWH);
            a[i][2] = *(const uint32_t*)(ap + 8);
            a[i][3] = *(const uint32_t*)(ap + 8 * ROWH + 8);
        }
        #pragma unroll
        for (int j = 0; j < 4; j++) {
            const __half* bp = Bs + (size_t)(wn * 32 + 8 * j + lr) * ROWH + lk + 16 * h;
            b[j][0] = *(const uint32_t*)(bp);
            b[j][1] = *(const uint32_t*)(bp + 8);
        }
        #pragma unroll
        for (int i = 0; i < 4; i++)
            #pragma unroll
            for (int j = 0; j < 4; j++)
                mma_f16(acc[i][j], a[i], b[j]);
    }
}

// ---------------- GEMM1 (mma, plain loads) ----------------
__global__ __launch_bounds__(256)
void gemm1_mma() {
    if (!g_useMMA) return;
    int row0 = blockIdx.y * 128;
    if (row0 >= g_pad_off[E_]) return;
    int e = 0;
    while (e < E_ - 1 && g_pad_off[e + 1] <= row0) e++;
    int f0  = blockIdx.x * 64;
    int tid = threadIdx.x, wid = tid >> 5, lane = tid & 31;
    int wm = wid >> 2, wn = wid & 3;

    __shared__ __align__(16) __half As[2][TILEH];
    __shared__ __align__(16) __half Bs[2][TILEH];

    // per-thread load slots: rows r and r+64, k-chunk ac
    int r  = tid >> 2;           // 0..63
    int ac = tid & 3;            // 16B chunk within 64B of K data

    const __half* pa0 = g_xp + (size_t)(row0 + r) * D_ + ac * 8;
    const __half* pa1 = pa0 + (size_t)64 * D_;

    int r1 = r + 64;
    int fA = f0 + ((r  >> 5) << 4) + (r  & 15);
    int fB = f0 + ((r1 >> 5) << 4) + (r1 & 15);
    const __half* srcA = ((r  >> 4) & 1) ? g_ut : g_gt;
    const __half* srcB = ((r1 >> 4) & 1) ? g_ut : g_gt;
    const __half* pb0 = srcA + ((size_t)e * F_ + fA) * D_ + ac * 8;
    const __half* pb1 = srcB + ((size_t)e * F_ + fB) * D_ + ac * 8;

    uint32_t sa0 = (uint32_t)r  * ROWH + ac * 8;
    uint32_t sa1 = (uint32_t)r1 * ROWH + ac * 8;

    float acc[4][4][4];
    #pragma unroll
    for (int i = 0; i < 4; i++)
        #pragma unroll
        for (int j = 0; j < 4; j++)
            #pragma unroll
            for (int q = 0; q < 4; q++) acc[i][j][q] = 0.0f;

    const int KT = D_ / BK;   // 32

    uint4 va0 = *(const uint4*)pa0, va1 = *(const uint4*)pa1;
    uint4 vb0 = *(const uint4*)pb0, vb1 = *(const uint4*)pb1;
    *(uint4*)(&As[0][sa0]) = va0;  *(uint4*)(&As[0][sa1]) = va1;
    *(uint4*)(&Bs[0][sa0]) = vb0;  *(uint4*)(&Bs[0][sa1]) = vb1;
    __syncthreads();

    #pragma unroll 1
    for (int k = 0; k < KT; k++) {
        if (k + 1 < KT) {
            pa0 += BK; pa1 += BK; pb0 += BK; pb1 += BK;
            va0 = *(const uint4*)pa0;  va1 = *(const uint4*)pa1;
            vb0 = *(const uint4*)pb0;  vb1 = *(const uint4*)pb1;
        }
        stage_mma(As[k & 1], Bs[k & 1], wm, wn, lane, acc);
        if (k + 1 < KT) {
            int nb = (k + 1) & 1;
            *(uint4*)(&As[nb][sa0]) = va0;  *(uint4*)(&As[nb][sa1]) = va1;
            *(uint4*)(&Bs[nb][sa0]) = vb0;  *(uint4*)(&Bs[nb][sa1]) = vb1;
            __syncthreads();
        }
    }

    // epilogue: SwiGLU -> fp16 act. j in {0,1}=gate, {2,3}=up (same f)
    #pragma unroll
    for (int i = 0; i < 4; i++)
        #pragma unroll
        for (int j = 0; j < 2; j++) {
            float* ga = acc[i][j];
            float* ua = acc[i][j + 2];
            int fb = f0 + wn * 16 + 8 * j + 2 * (lane & 3);
            #pragma unroll
            for (int hr = 0; hr < 2; hr++) {
                int m = row0 + wm * 64 + 16 * i + (lane >> 2) + 8 * hr;
                float g0 = ga[2 * hr + 0], g1v = ga[2 * hr + 1];
                float u0 = ua[2 * hr + 0], u1v = ua[2 * hr + 1];
                float a0 = (g0 / (1.0f + __expf(-g0))) * u0;
                float a1 = (g1v / (1.0f + __expf(-g1v))) * u1v;
                *(__half2*)(g_act + (size_t)m * F_ + fb) =
                    __halves2half2(__float2half(a0), __float2half(a1));
            }
        }
}

// ---------------- GEMM2 (mma, plain loads) ----------------
__global__ __launch_bounds__(256)
void gemm2_mma() {
    if (!g_useMMA) return;
    int row0 = blockIdx.y * 128;
    if (row0 >= g_pad_off[E_]) return;
    int e = 0;
    while (e < E_ - 1 && g_pad_off[e + 1] <= row0) e++;
    int n0  = blockIdx.x * 128;
    int tid = threadIdx.x, wid = tid >> 5, lane = tid & 31;
    int wm = wid >> 2, wn = wid & 3;

    __shared__ __align__(16) __half As[2][TILEH];
    __shared__ __align__(16) __half Bs[2][TILEH];

    int r  = tid >> 2;
    int ac = tid & 3;
    int r1 = r + 64;

    const __half* pa0 = g_act + (size_t)(row0 + r) * F_ + ac * 8;
    const __half* pa1 = pa0 + (size_t)64 * F_;
    const __half* pb0 = g_dt + ((size_t)e * D_ + n0 + r)  * F_ + ac * 8;
    const __half* pb1 = g_dt + ((size_t)e * D_ + n0 + r1) * F_ + ac * 8;

    uint32_t sa0 = (uint32_t)r  * ROWH + ac * 8;
    uint32_t sa1 = (uint32_t)r1 * ROWH + ac * 8;

    float acc[4][4][4];
    #pragma unroll
    for (int i = 0; i < 4; i++)
        #pragma unroll
        for (int j = 0; j < 4; j++)
            #pragma unroll
            for (int q = 0; q < 4; q++) acc[i][j][q] = 0.0f;

    const int KT = F_ / BK;   // 88

    uint4 va0 = *(const uint4*)pa0, va1 = *(const uint4*)pa1;
    uint4 vb0 = *(const uint4*)pb0, vb1 = *(const uint4*)pb1;
    *(uint4*)(&As[0][sa0]) = va0;  *(uint4*)(&As[0][sa1]) = va1;
    *(uint4*)(&Bs[0][sa0]) = vb0;  *(uint4*)(&Bs[0][sa1]) = vb1;
    __syncthreads();

    #pragma unroll 1
    for (int k = 0; k < KT; k++) {
        if (k + 1 < KT) {
            pa0 += BK; pa1 += BK; pb0 += BK; pb1 += BK;
            va0 = *(const uint4*)pa0;  va1 = *(const uint4*)pa1;
            vb0 = *(const uint4*)pb0;  vb1 = *(const uint4*)pb1;
        }
        stage_mma(As[k & 1], Bs[k & 1], wm, wn, lane, acc);
        if (k + 1 < KT) {
            int nb = (k + 1) & 1;
            *(uint4*)(&As[nb][sa0]) = va0;  *(uint4*)(&As[nb][sa1]) = va1;
            *(uint4*)(&Bs[nb][sa0]) = vb0;  *(uint4*)(&Bs[nb][sa1]) = vb1;
            __syncthreads();
        }
    }

    #pragma unroll
    for (int i = 0; i < 4; i++) {
        float wr[2];
        #pragma unroll
        for (int hr = 0; hr < 2; hr++)
            wr[hr] = g_perm_w[row0 + wm * 64 + 16 * i + (lane >> 2) + 8 * hr];
        #pragma unroll
        for (int j = 0; j < 4; j++) {
            int n = n0 + wn * 32 + 8 * j + 2 * (lane & 3);
            #pragma unroll
            for (int hr = 0; hr < 2; hr++) {
                int m = row0 + wm * 64 + 16 * i + (lane >> 2) + 8 * hr;
                float2 v;
                v.x = acc[i][j][2 * hr + 0] * wr[hr];
                v.y = acc[i][j][2 * hr + 1] * wr[hr];
                *(float2*)(g_y2 + (size_t)m * D_ + n) = v;
            }
        }
    }
}

// ---------------- probes ----------------
__global__ void probeA_kernel() {
    int i = blockIdx.x * 256 + threadIdx.x;
    if (i >= PROBE_ACT) return;
    if (((const uint16_t*)g_act)[i] != 0) g_flagA = 1;
}
__global__ void probeB_kernel() {
    int i = blockIdx.x * 256 + threadIdx.x;
    if (i >= PROBE_Y2) return;
    if (((const uint32_t*)g_y2)[i] != 0) g_flagB = 1;
}

// ---------------- SIMT fallbacks ----------------
#define SBM 64
#define SBN 64
#define SBK 16

__global__ __launch_bounds__(256)
void gemm1_simt(const float* __restrict__ x,
                const float* __restrict__ gate_w,
                const float* __restrict__ up_w) {
    if (g_flagA) return;
    int row0 = blockIdx.y * SBM;
    if (row0 >= g_pad_off[E_]) return;
    int e = 0;
    while (e < E_ - 1 && g_pad_off[e + 1] <= row0) e++;
    const float* G = gate_w + (size_t)e * D_ * F_;
    const float* U = up_w   + (size_t)e * D_ * F_;
    int n0 = blockIdx.x * SBN;

    __shared__ float As2[SBK][SBM + 4];
    __shared__ float Bg[SBK][SBN];
    __shared__ float Bu[SBK][SBN];

    int tid   = threadIdx.x;
    int a_row = tid >> 2;
    int a_k   = (tid & 3) * 4;
    int tok   = g_perm_token[row0 + a_row];
    bool valid = (tok >= 0);
    const float* xrow = x + (size_t)(valid ? tok : 0) * D_;

    int b_k = tid >> 4;
    int b_n = (tid & 15) * 4;
    int ty = tid >> 4, tx = tid & 15;

    float ag[4][4] = {}, au[4][4] = {};

    for (int k0 = 0; k0 < D_; k0 += SBK) {
        float4 av = valid ? *(const float4*)(xrow + k0 + a_k)
                          : make_float4(0.f, 0.f, 0.f, 0.f);
        As2[a_k + 0][a_row] = av.x;  As2[a_k + 1][a_row] = av.y;
        As2[a_k + 2][a_row] = av.z;  As2[a_k + 3][a_row] = av.w;
        *(float4*)&Bg[b_k][b_n] = *(const float4*)(G + (size_t)(k0 + b_k) * F_ + n0 + b_n);
        *(float4*)&Bu[b_k][b_n] = *(const float4*)(U + (size_t)(k0 + b_k) * F_ + n0 + b_n);
        __syncthreads();
        #pragma unroll
        for (int kk = 0; kk < SBK; kk++) {
            float4 a4 = *(const float4*)&As2[kk][ty * 4];
            float4 g4 = *(const float4*)&Bg[kk][tx * 4];
            float4 u4 = *(const float4*)&Bu[kk][tx * 4];
            float am[4] = {a4.x, a4.y, a4.z, a4.w};
            float gm[4] = {g4.x, g4.y, g4.z, g4.w};
            float um[4] = {u4.x, u4.y, u4.z, u4.w};
            #pragma unroll
            for (int i = 0; i < 4; i++)
                #pragma unroll
                for (int j = 0; j < 4; j++) {
                    ag[i][j] += am[i] * gm[j];
                    au[i][j] += am[i] * um[j];
                }
        }
        __syncthreads();
    }

    #pragma unroll
    for (int i = 0; i < 4; i++) {
        int rI = row0 + ty * 4 + i;
        size_t base = (size_t)rI * F_ + n0 + tx * 4;
        #pragma unroll
        for (int j = 0; j < 4; j++) {
            float g = ag[i][j], u = au[i][j];
            g_act[base + j] = __float2half((g / (1.0f + __expf(-g))) * u);
        }
    }
}

__global__ __launch_bounds__(256)
void gemm2_simt(const float* __restrict__ down_w) {
    if (g_flagB) return;
    int row0 = blockIdx.y * SBM;
    if (row0 >= g_pad_off[E_]) return;
    int e = 0;
    while (e < E_ - 1 && g_pad_off[e + 1] <= row0) e++;
    const float* Wd = down_w + (size_t)e * F_ * D_;
    int n0 = blockIdx.x * SBN;

    __shared__ float As2[SBK][SBM + 4];
    __shared__ float Bs2[SBK][SBN];

    int tid   = threadIdx.x;
    int a_row = tid >> 2;
    int a_k   = (tid & 3) * 4;
    size_t abase = (size_t)(row0 + a_row) * F_;

    int b_k = tid >> 4;
    int b_n = (tid & 15) * 4;
    int ty = tid >> 4, tx = tid & 15;

    float acc[4][4] = {};

    for (int k0 = 0; k0 < F_; k0 += SBK) {
        #pragma unroll
        for (int q = 0; q < 4; q++)
            As2[a_k + q][a_row] = __half2float(g_act[abase + k0 + a_k + q]);
        *(float4*)&Bs2[b_k][b_n] = *(const float4*)(Wd + (size_t)(k0 + b_k) * D_ + n0 + b_n);
        __syncthreads();
        #pragma unroll
        for (int kk = 0; kk < SBK; kk++) {
            float4 a4 = *(const float4*)&As2[kk][ty * 4];
            float4 b4 = *(const float4*)&Bs2[kk][tx * 4];
            float am[4] = {a4.x, a4.y, a4.z, a4.w};
            float bm[4] = {b4.x, b4.y, b4.z, b4.w};
            #pragma unroll
            for (int i = 0; i < 4; i++)
                #pragma unroll
                for (int j = 0; j < 4; j++)
                    acc[i][j] += am[i] * bm[j];
        }
        __syncthreads();
    }

    #pragma unroll
    for (int i = 0; i < 4; i++) {
        int rI = row0 + ty * 4 + i;
        float w = g_perm_w[rI];
        float* yrow = g_y2 + (size_t)rI * D_ + n0 + tx * 4;
        #pragma unroll
        for (int j = 0; j < 4; j++)
            yrow[j] = acc[i][j] * w;
    }
}

// ---------------- combine ----------------
__global__ void combine_kernel(float* __restrict__ out) {
    int i = blockIdx.x * 256 + threadIdx.x;
    if (i >= OUT_ELEMS) return;
    int t = i >> 10, d = i & 1023;
    int s0 = g_tok_slot[t * 2 + 0];
    int s1 = g_tok_slot[t * 2 + 1];
    out[i] = g_y2[(size_t)s0 * D_ + d] + g_y2[(size_t)s1 * D_ + d];
}

// ---------------- launch ----------------
extern "C" void kernel_launch(void* const* d_in, const int* in_sizes, int n_in,
                              void* d_out, int out_size) {
    const float* x      = (const float*)d_in[0];
    const float* rw     = (const float*)d_in[1];
    const float* gate_w = (const float*)d_in[2];
    const float* up_w   = (const float*)d_in[3];
    const float* down_w = (const float*)d_in[4];
    float* out = (float*)d_out;

    mma_selftest<<<1, 32>>>();
    init_kernel<<<(PROBE_ACT + 255) / 256, 256>>>();
    router_kernel<<<NTOK, 256>>>(x, rw);
    scan_kernel<<<1, 1>>>();
    fill_kernel<<<(NSLOT + 255) / 256, 256>>>();
    xgather_kernel<<<SLOT_PAD, 256>>>(x);

    {
        dim3 blk(32, 8);
        dim3 g_gu(F_ / 32, D_ / 32, E_);
        tconv_kernel<<<g_gu, blk>>>(gate_w, g_gt, D_, F_);
        tconv_kernel<<<g_gu, blk>>>(up_w,   g_ut, D_, F_);
        dim3 g_d(D_ / 32, F_ / 32, E_);
        tconv_kernel<<<g_d, blk>>>(down_w,  g_dt, F_, D_);
    }

    dim3 g1m(F_ / 64, SLOT_PAD / 128);   // 44 x 136
    gemm1_mma<<<g1m, 256>>>();
    probeA_kernel<<<(PROBE_ACT + 255) / 256, 256>>>();
    dim3 g1s(F_ / SBN, SLOT_PAD / SBM);
    gemm1_simt<<<g1s, 256>>>(x, gate_w, up_w);

    dim3 g2m(D_ / 128, SLOT_PAD / 128);  // 8 x 136
    gemm2_mma<<<g2m, 256>>>();
    probeB_kernel<<<(PROBE_Y2 + 255) / 256, 256>>>();
    dim3 g2s(D_ / SBN, SLOT_PAD / SBM);
    gemm2_simt<<<g2s, 256>>>(down_w);

    combine_kernel<<<(OUT_ELEMS + 255) / 256, 256>>>(out);
}

// round 9
// speedup vs baseline: 1.1851x; 1.1851x over previous
#include <cuda_runtime.h>
#include <math.h>
#include <stdint.h>

// ---------------- problem constants ----------------
#define E_        8
#define NTOK      8192
#define D_        1024
#define F_        2816
#define NSLOT     (NTOK * 2)
#define SLOT_PAD  (NSLOT + E_ * 128)   // 17408, expert ranges 128-aligned
#define OUT_ELEMS (NTOK * D_)

#define BKS 8                           // K per stage

typedef unsigned long long u64;

// ---------------- static device scratch ----------------
__device__ __align__(128) float g_act[(size_t)SLOT_PAD * F_];   // SwiGLU activations
__device__ __align__(128) float g_y2[(size_t)SLOT_PAD * D_];    // weighted expert outputs

__device__ int   g_perm_token[SLOT_PAD];
__device__ float g_perm_w[SLOT_PAD];
__device__ int   g_tok_slot[NSLOT];
__device__ int   g_counts[E_];
__device__ int   g_cursor[E_];
__device__ int   g_pad_off[E_ + 1];
__device__ int   g_topk_idx[NSLOT];
__device__ float g_topk_w[NSLOT];

// ---------------- f32x2 helpers ----------------
static __device__ __forceinline__ void fma2(u64& d, u64 a, u64 b) {
    asm("fma.rn.f32x2 %0, %1, %2, %0;" : "+l"(d) : "l"(a), "l"(b));
}
static __device__ __forceinline__ float2 unpack2(u64 v) {
    float2 f;
    asm("mov.b64 {%0, %1}, %2;" : "=f"(f.x), "=f"(f.y) : "l"(v));
    return f;
}

// ---------------- pre-pass kernels (proven) ----------------
__global__ void init_kernel() {
    int i = blockIdx.x * 256 + threadIdx.x;
    if (i < SLOT_PAD) { g_perm_token[i] = -1; g_perm_w[i] = 0.0f; }
    if (i < E_) g_counts[i] = 0;
}

__global__ void router_kernel(const float* __restrict__ x, const float* __restrict__ rw) {
    int t = blockIdx.x;
    const float* xr = x + (size_t)t * D_;
    int lane = threadIdx.x & 31;
    int w    = threadIdx.x >> 5;

    double s = 0.0;
    for (int d = lane; d < D_; d += 32)
        s += (double)xr[d] * (double)rw[d * E_ + w];
    #pragma unroll
    for (int o = 16; o > 0; o >>= 1)
        s += __shfl_down_sync(0xffffffffu, s, o);

    __shared__ double sc[E_];
    if (lane == 0) sc[w] = s;
    __syncthreads();

    if (threadIdx.x == 0) {
        double m = sc[0];
        #pragma unroll
        for (int e = 1; e < E_; e++) m = fmax(m, sc[e]);
        double p[E_], sum = 0.0;
        #pragma unroll
        for (int e = 0; e < E_; e++) { p[e] = exp(sc[e] - m); sum += p[e]; }
        #pragma unroll
        for (int e = 0; e < E_; e++) p[e] /= sum;
        int i0 = 0;
        #pragma unroll
        for (int e = 1; e < E_; e++) if (p[e] > p[i0]) i0 = e;
        int i1 = (i0 == 0) ? 1 : 0;
        #pragma unroll
        for (int e = 0; e < E_; e++) { if (e == i0) continue; if (p[e] > p[i1]) i1 = e; }
        float p0 = (float)p[i0], p1 = (float)p[i1];
        float inv = 1.0f / (p0 + p1);
        g_topk_idx[t * 2 + 0] = i0;  g_topk_idx[t * 2 + 1] = i1;
        g_topk_w[t * 2 + 0] = p0 * inv;  g_topk_w[t * 2 + 1] = p1 * inv;
        atomicAdd(&g_counts[i0], 1);
        atomicAdd(&g_counts[i1], 1);
    }
}

__global__ void scan_kernel() {
    int off = 0;
    #pragma unroll
    for (int e = 0; e < E_; e++) {
        g_pad_off[e] = off;  g_cursor[e] = off;
        off += (g_counts[e] + 127) & ~127;
    }
    g_pad_off[E_] = off;
}

__global__ void fill_kernel() {
    int idx = blockIdx.x * blockDim.x + threadIdx.x;
    if (idx >= NSLOT) return;
    int e    = g_topk_idx[idx];
    int slot = atomicAdd(&g_cursor[e], 1);
    g_perm_token[slot] = idx >> 1;
    g_perm_w[slot]     = g_topk_w[idx];
    g_tok_slot[idx]    = slot;
}

// =====================================================================
// GEMM1: act = silu(x@G) * (x@U)
// CTA: 128 rows x 64 f (gate AND up for those f = 128 output cols).
// smem: A duplicated pairs [BKS][256], Bg/Bu [BKS][64]; double buffered.
// thread: ty=tid>>4 -> rows 8ty..8ty+7 ; tx=tid&15 -> f 4tx..4tx+3
// =====================================================================
__global__ __launch_bounds__(256, 2)
void gemm1_kernel(const float* __restrict__ x,
                  const float* __restrict__ gate_w,
                  const float* __restrict__ up_w) {
    int row0 = blockIdx.y * 128;
    if (row0 >= g_pad_off[E_]) return;
    int e = 0;
    while (e < E_ - 1 && g_pad_off[e + 1] <= row0) e++;
    int f0 = blockIdx.x * 64;

    __shared__ float As[2][BKS][256];
    __shared__ float Bg[2][BKS][64];
    __shared__ float Bu[2][BKS][64];

    int tid = threadIdx.x;
    int ty = tid >> 4, tx = tid & 15;

    // A loader: row = tid&127, k quartet = (tid>>7)*4
    int arow = tid & 127;
    int akq  = (tid >> 7) * 4;
    int tok  = g_perm_token[row0 + arow];
    bool valid = (tok >= 0);
    const float* xrow = x + (size_t)(valid ? tok : 0) * D_ + akq;

    // B loader: mat = tid>>7, k = (tid>>4)&7, f quartet = (tid&15)*4
    int bmat = tid >> 7;
    int bk   = (tid >> 4) & 7;
    int bf   = (tid & 15) * 4;
    const float* bsrc = (bmat ? up_w : gate_w) +
                        ((size_t)e * D_ + bk) * F_ + f0 + bf;

    u64 accg[8][2], accu[8][2];
    #pragma unroll
    for (int i = 0; i < 8; i++) {
        accg[i][0] = 0ull; accg[i][1] = 0ull;
        accu[i][0] = 0ull; accu[i][1] = 0ull;
    }

    const int NSTG = D_ / BKS;   // 128

    float4 av = valid ? *(const float4*)xrow : make_float4(0.f, 0.f, 0.f, 0.f);
    float4 bv = *(const float4*)bsrc;
    {
        float va[4] = {av.x, av.y, av.z, av.w};
        #pragma unroll
        for (int q = 0; q < 4; q++)
            *(float2*)&As[0][akq + q][2 * arow] = make_float2(va[q], va[q]);
        if (bmat) *(float4*)&Bu[0][bk][bf] = bv;
        else      *(float4*)&Bg[0][bk][bf] = bv;
    }
    __syncthreads();

    #pragma unroll 1
    for (int s = 0; s < NSTG; s++) {
        int cur = s & 1;
        if (s + 1 < NSTG) {
            av = valid ? *(const float4*)(xrow + (s + 1) * BKS)
                       : make_float4(0.f, 0.f, 0.f, 0.f);
            bv = *(const float4*)(bsrc + (size_t)(s + 1) * BKS * F_);
        }
        #pragma unroll
        for (int k = 0; k < BKS; k++) {
            ulonglong2 A01 = *(const ulonglong2*)&As[cur][k][16 * ty + 0];
            ulonglong2 A23 = *(const ulonglong2*)&As[cur][k][16 * ty + 4];
            ulonglong2 A45 = *(const ulonglong2*)&As[cur][k][16 * ty + 8];
            ulonglong2 A67 = *(const ulonglong2*)&As[cur][k][16 * ty + 12];
            ulonglong2 Gp = *(const ulonglong2*)&Bg[cur][k][4 * tx];
            ulonglong2 Up = *(const ulonglong2*)&Bu[cur][k][4 * tx];
            u64 ap[8] = {A01.x, A01.y, A23.x, A23.y, A45.x, A45.y, A67.x, A67.y};
            #pragma unroll
            for (int i = 0; i < 8; i++) {
                fma2(accg[i][0], ap[i], Gp.x);
                fma2(accg[i][1], ap[i], Gp.y);
                fma2(accu[i][0], ap[i], Up.x);
                fma2(accu[i][1], ap[i], Up.y);
            }
        }
        if (s + 1 < NSTG) {
            __syncthreads();
            int nxt = cur ^ 1;
            float va[4] = {av.x, av.y, av.z, av.w};
            #pragma unroll
            for (int q = 0; q < 4; q++)
                *(float2*)&As[nxt][akq + q][2 * arow] = make_float2(va[q], va[q]);
            if (bmat) *(float4*)&Bu[nxt][bk][bf] = bv;
            else      *(float4*)&Bg[nxt][bk][bf] = bv;
            __syncthreads();
        }
    }

    // epilogue: SwiGLU, fp32 act
    #pragma unroll
    for (int i = 0; i < 8; i++) {
        int m = row0 + 8 * ty + i;
        float* arow_o = g_act + (size_t)m * F_ + f0 + 4 * tx;
        #pragma unroll
        for (int p = 0; p < 2; p++) {
            float2 g = unpack2(accg[i][p]);
            float2 u = unpack2(accu[i][p]);
            float2 o;
            o.x = (g.x / (1.0f + __expf(-g.x))) * u.x;
            o.y = (g.y / (1.0f + __expf(-g.y))) * u.y;
            *(float2*)(arow_o + 2 * p) = o;
        }
    }
}

// =====================================================================
// GEMM2: y2 = w * (act @ Wdown)
// CTA: 128 rows x 128 d-cols. thread: 8 rows x 8 cols.
// =====================================================================
__global__ __launch_bounds__(256, 2)
void gemm2_kernel(const float* __restrict__ down_w) {
    int row0 = blockIdx.y * 128;
    if (row0 >= g_pad_off[E_]) return;
    int e = 0;
    while (e < E_ - 1 && g_pad_off[e + 1] <= row0) e++;
    int n0 = blockIdx.x * 128;

    __shared__ float As[2][BKS][256];
    __shared__ float Bn[2][BKS][128];

    int tid = threadIdx.x;
    int ty = tid >> 4, tx = tid & 15;

    int arow = tid & 127;
    int akq  = (tid >> 7) * 4;
    const float* arow_g = g_act + (size_t)(row0 + arow) * F_ + akq;

    int bk = tid >> 5;               // 0..7
    int bn = (tid & 31) * 4;         // 0..124
    const float* bsrc = down_w + ((size_t)e * F_ + bk) * D_ + n0 + bn;

    u64 acc[8][4];
    #pragma unroll
    for (int i = 0; i < 8; i++)
        #pragma unroll
        for (int p = 0; p < 4; p++) acc[i][p] = 0ull;

    const int NSTG = F_ / BKS;   // 352

    float4 av = *(const float4*)arow_g;
    float4 bv = *(const float4*)bsrc;
    {
        float va[4] = {av.x, av.y, av.z, av.w};
        #pragma unroll
        for (int q = 0; q < 4; q++)
            *(float2*)&As[0][akq + q][2 * arow] = make_float2(va[q], va[q]);
        *(float4*)&Bn[0][bk][bn] = bv;
    }
    __syncthreads();

    #pragma unroll 1
    for (int s = 0; s < NSTG; s++) {
        int cur = s & 1;
        if (s + 1 < NSTG) {
            av = *(const float4*)(arow_g + (s + 1) * BKS);
            bv = *(const float4*)(bsrc + (size_t)(s + 1) * BKS * D_);
        }
        #pragma unroll
        for (int k = 0; k < BKS; k++) {
            ulonglong2 A01 = *(const ulonglong2*)&As[cur][k][16 * ty + 0];
            ulonglong2 A23 = *(const ulonglong2*)&As[cur][k][16 * ty + 4];
            ulonglong2 A45 = *(const ulonglong2*)&As[cur][k][16 * ty + 8];
            ulonglong2 A67 = *(const ulonglong2*)&As[cur][k][16 * ty + 12];
            ulonglong2 B01 = *(const ulonglong2*)&Bn[cur][k][8 * tx + 0];
            ulonglong2 B23 = *(const ulonglong2*)&Bn[cur][k][8 * tx + 4];
            u64 ap[8] = {A01.x, A01.y, A23.x, A23.y, A45.x, A45.y, A67.x, A67.y};
            u64 bp[4] = {B01.x, B01.y, B23.x, B23.y};
            #pragma unroll
            for (int i = 0; i < 8; i++)
                #pragma unroll
                for (int p = 0; p < 4; p++)
                    fma2(acc[i][p], ap[i], bp[p]);
        }
        if (s + 1 < NSTG) {
            __syncthreads();
            int nxt = cur ^ 1;
            float va[4] = {av.x, av.y, av.z, av.w};
            #pragma unroll
            for (int q = 0; q < 4; q++)
                *(float2*)&As[nxt][akq + q][2 * arow] = make_float2(va[q], va[q]);
            *(float4*)&Bn[nxt][bk][bn] = bv;
            __syncthreads();
        }
    }

    // epilogue: scale by routing weight, deterministic y2 store
    #pragma unroll
    for (int i = 0; i < 8; i++) {
        int r = row0 + 8 * ty + i;
        float w = g_perm_w[r];
        float* yrow = g_y2 + (size_t)r * D_ + n0 + 8 * tx;
        #pragma unroll
        for (int p = 0; p < 4; p++) {
            float2 v = unpack2(acc[i][p]);
            v.x *= w;  v.y *= w;
            *(float2*)(yrow + 2 * p) = v;
        }
    }
}

// ---------------- combine: out[t] = y2[slot0] + y2[slot1] ----------------
__global__ void combine_kernel(float* __restrict__ out) {
    int i = blockIdx.x * 256 + threadIdx.x;
    if (i >= OUT_ELEMS) return;
    int t = i >> 10, d = i & 1023;
    int s0 = g_tok_slot[t * 2 + 0];
    int s1 = g_tok_slot[t * 2 + 1];
    out[i] = g_y2[(size_t)s0 * D_ + d] + g_y2[(size_t)s1 * D_ + d];
}

// ---------------- launch ----------------
extern "C" void kernel_launch(void* const* d_in, const int* in_sizes, int n_in,
                              void* d_out, int out_size) {
    const float* x      = (const float*)d_in[0];
    const float* rw     = (const float*)d_in[1];
    const float* gate_w = (const float*)d_in[2];
    const float* up_w   = (const float*)d_in[3];
    const float* down_w = (const float*)d_in[4];
    float* out = (float*)d_out;

    init_kernel<<<(SLOT_PAD + 255) / 256, 256>>>();
    router_kernel<<<NTOK, 256>>>(x, rw);
    scan_kernel<<<1, 1>>>();
    fill_kernel<<<(NSLOT + 255) / 256, 256>>>();

    dim3 g1(F_ / 64, SLOT_PAD / 128);    // 44 x 136
    gemm1_kernel<<<g1, 256>>>(x, gate_w, up_w);

    dim3 g2(D_ / 128, SLOT_PAD / 128);   // 8 x 136
    gemm2_kernel<<<g2, 256>>>(down_w);

    combine_kernel<<<(OUT_ELEMS + 255) / 256, 256>>>(out);
}

// round 10
// speedup vs baseline: 1.3271x; 1.1198x over previous
#include <cuda_runtime.h>
#include <math.h>
#include <stdint.h>

// ---------------- problem constants ----------------
#define E_        8
#define NTOK      8192
#define D_        1024
#define F_        2816
#define NSLOT     (NTOK * 2)
#define SLOT_PAD  (NSLOT + E_ * 128)   // 17408, expert ranges 128-aligned
#define OUT_ELEMS (NTOK * D_)

#define BK 16                           // K per stage
#define NB 3                            // triple buffer, one sync per stage

// ---------------- static device scratch ----------------
__device__ __align__(128) float g_act[(size_t)SLOT_PAD * F_];
__device__ __align__(128) float g_y2[(size_t)SLOT_PAD * D_];

__device__ int   g_perm_token[SLOT_PAD];
__device__ float g_perm_w[SLOT_PAD];
__device__ int   g_tok_slot[NSLOT];
__device__ int   g_counts[E_];
__device__ int   g_cursor[E_];
__device__ int   g_pad_off[E_ + 1];
__device__ int   g_topk_idx[NSLOT];
__device__ float g_topk_w[NSLOT];

// ---------------- pre-pass kernels (proven) ----------------
__global__ void init_kernel() {
    int i = blockIdx.x * 256 + threadIdx.x;
    if (i < SLOT_PAD) { g_perm_token[i] = -1; g_perm_w[i] = 0.0f; }
    if (i < E_) g_counts[i] = 0;
}

__global__ void router_kernel(const float* __restrict__ x, const float* __restrict__ rw) {
    int t = blockIdx.x;
    const float* xr = x + (size_t)t * D_;
    int lane = threadIdx.x & 31;
    int w    = threadIdx.x >> 5;

    double s = 0.0;
    for (int d = lane; d < D_; d += 32)
        s += (double)xr[d] * (double)rw[d * E_ + w];
    #pragma unroll
    for (int o = 16; o > 0; o >>= 1)
        s += __shfl_down_sync(0xffffffffu, s, o);

    __shared__ double sc[E_];
    if (lane == 0) sc[w] = s;
    __syncthreads();

    if (threadIdx.x == 0) {
        double m = sc[0];
        #pragma unroll
        for (int e = 1; e < E_; e++) m = fmax(m, sc[e]);
        double p[E_], sum = 0.0;
        #pragma unroll
        for (int e = 0; e < E_; e++) { p[e] = exp(sc[e] - m); sum += p[e]; }
        #pragma unroll
        for (int e = 0; e < E_; e++) p[e] /= sum;
        int i0 = 0;
        #pragma unroll
        for (int e = 1; e < E_; e++) if (p[e] > p[i0]) i0 = e;
        int i1 = (i0 == 0) ? 1 : 0;
        #pragma unroll
        for (int e = 0; e < E_; e++) { if (e == i0) continue; if (p[e] > p[i1]) i1 = e; }
        float p0 = (float)p[i0], p1 = (float)p[i1];
        float inv = 1.0f / (p0 + p1);
        g_topk_idx[t * 2 + 0] = i0;  g_topk_idx[t * 2 + 1] = i1;
        g_topk_w[t * 2 + 0] = p0 * inv;  g_topk_w[t * 2 + 1] = p1 * inv;
        atomicAdd(&g_counts[i0], 1);
        atomicAdd(&g_counts[i1], 1);
    }
}

__global__ void scan_kernel() {
    int off = 0;
    #pragma unroll
    for (int e = 0; e < E_; e++) {
        g_pad_off[e] = off;  g_cursor[e] = off;
        off += (g_counts[e] + 127) & ~127;
    }
    g_pad_off[E_] = off;
}

__global__ void fill_kernel() {
    int idx = blockIdx.x * blockDim.x + threadIdx.x;
    if (idx >= NSLOT) return;
    int e    = g_topk_idx[idx];
    int slot = atomicAdd(&g_cursor[e], 1);
    g_perm_token[slot] = idx >> 1;
    g_perm_w[slot]     = g_topk_w[idx];
    g_tok_slot[idx]    = slot;
}

// =====================================================================
// GEMM1: act = silu(x@G) * (x@U)
// CTA: 128 slot-rows x 64 f (both gate & up). 256 threads, 8m x 4f x 2mats.
// smem: As[NB][BK][128], Bg[NB][BK][64], Bu[NB][BK][64] = 48KB.
// Triple buffer, register-staged global loads, ONE syncthreads per stage.
// =====================================================================
__global__ __launch_bounds__(256, 1)
void gemm1_kernel(const float* __restrict__ x,
                  const float* __restrict__ gate_w,
                  const float* __restrict__ up_w) {
    int row0 = blockIdx.y * 128;
    if (row0 >= g_pad_off[E_]) return;
    int e = 0;
    while (e < E_ - 1 && g_pad_off[e + 1] <= row0) e++;
    const float* G = gate_w + (size_t)e * D_ * F_;
    const float* U = up_w   + (size_t)e * D_ * F_;
    int f0 = blockIdx.x * 64;

    __shared__ float As[NB][BK][128];
    __shared__ float Bg[NB][BK][64];
    __shared__ float Bu[NB][BK][64];

    int tid = threadIdx.x;
    int ty = tid >> 4, tx = tid & 15;     // 8 rows / 4 f-cols per thread

    // A loader: row ar (0..127), k-octet ak8 (0 or 8)
    int ar  = tid & 127;
    int ak8 = (tid >> 7) * 8;
    int tok = g_perm_token[row0 + ar];
    bool valid = (tok >= 0);
    const float* xrow = x + (size_t)(valid ? tok : 0) * D_ + ak8;

    // B loader: k-row bk (0..15), f-quartet bf
    int bk = tid >> 4;
    int bf = (tid & 15) * 4;
    const float* gp = G + ((size_t)bk) * F_ + f0 + bf;
    const float* up = U + ((size_t)bk) * F_ + f0 + bf;

    float accg[8][4], accu[8][4];
    #pragma unroll
    for (int i = 0; i < 8; i++)
        #pragma unroll
        for (int j = 0; j < 4; j++) { accg[i][j] = 0.f; accu[i][j] = 0.f; }

    const int NS = D_ / BK;   // 64

    float4 ra0, ra1, rg, ru;
    // prologue: stage 0 -> buf0
    ra0 = valid ? *(const float4*)(xrow)     : make_float4(0, 0, 0, 0);
    ra1 = valid ? *(const float4*)(xrow + 4) : make_float4(0, 0, 0, 0);
    rg  = *(const float4*)(gp);
    ru  = *(const float4*)(up);
    {
        float a[8] = {ra0.x, ra0.y, ra0.z, ra0.w, ra1.x, ra1.y, ra1.z, ra1.w};
        #pragma unroll
        for (int q = 0; q < 8; q++) As[0][ak8 + q][ar] = a[q];
        *(float4*)&Bg[0][bk][bf] = rg;
        *(float4*)&Bu[0][bk][bf] = ru;
    }
    // hold stage 1 in regs
    ra0 = valid ? *(const float4*)(xrow + BK)     : make_float4(0, 0, 0, 0);
    ra1 = valid ? *(const float4*)(xrow + BK + 4) : make_float4(0, 0, 0, 0);
    rg  = *(const float4*)(gp + (size_t)BK * F_);
    ru  = *(const float4*)(up + (size_t)BK * F_);
    __syncthreads();

    #pragma unroll 1
    for (int s = 0; s < NS; s++) {
        int cb = s % NB;
        if (s + 1 < NS) {
            int nb = (s + 1) % NB;
            float a[8] = {ra0.x, ra0.y, ra0.z, ra0.w, ra1.x, ra1.y, ra1.z, ra1.w};
            #pragma unroll
            for (int q = 0; q < 8; q++) As[nb][ak8 + q][ar] = a[q];
            *(float4*)&Bg[nb][bk][bf] = rg;
            *(float4*)&Bu[nb][bk][bf] = ru;
        }
        if (s + 2 < NS) {
            int k0 = (s + 2) * BK;
            ra0 = valid ? *(const float4*)(xrow + k0)     : make_float4(0, 0, 0, 0);
            ra1 = valid ? *(const float4*)(xrow + k0 + 4) : make_float4(0, 0, 0, 0);
            rg  = *(const float4*)(gp + (size_t)k0 * F_);
            ru  = *(const float4*)(up + (size_t)k0 * F_);
        }
        __syncthreads();
        #pragma unroll
        for (int k = 0; k < BK; k++) {
            float4 a04 = *(const float4*)&As[cb][k][8 * ty];
            float4 a48 = *(const float4*)&As[cb][k][8 * ty + 4];
            float4 bg4 = *(const float4*)&Bg[cb][k][4 * tx];
            float4 bu4 = *(const float4*)&Bu[cb][k][4 * tx];
            float a[8] = {a04.x, a04.y, a04.z, a04.w, a48.x, a48.y, a48.z, a48.w};
            float bg[4] = {bg4.x, bg4.y, bg4.z, bg4.w};
            float bu[4] = {bu4.x, bu4.y, bu4.z, bu4.w};
            #pragma unroll
            for (int i = 0; i < 8; i++)
                #pragma unroll
                for (int j = 0; j < 4; j++) {
                    accg[i][j] += a[i] * bg[j];
                    accu[i][j] += a[i] * bu[j];
                }
        }
    }

    // epilogue: SwiGLU -> fp32 act
    #pragma unroll
    for (int i = 0; i < 8; i++) {
        int m = row0 + 8 * ty + i;
        float4 o;
        float* po = (float*)&o;
        #pragma unroll
        for (int j = 0; j < 4; j++) {
            float g = accg[i][j], u = accu[i][j];
            po[j] = (g / (1.0f + __expf(-g))) * u;
        }
        *(float4*)(g_act + (size_t)m * F_ + f0 + 4 * tx) = o;
    }
}

// =====================================================================
// GEMM2: y2 = w * (act @ Wdown)
// CTA: 128 slot-rows x 128 d. 256 threads, 8m x 8d per thread.
// smem: As[NB][BK][128], Bs[NB][BK][128] = 48KB. Same pipeline.
// =====================================================================
__global__ __launch_bounds__(256, 1)
void gemm2_kernel(const float* __restrict__ down_w) {
    int row0 = blockIdx.y * 128;
    if (row0 >= g_pad_off[E_]) return;
    int e = 0;
    while (e < E_ - 1 && g_pad_off[e + 1] <= row0) e++;
    const float* Wd = down_w + (size_t)e * F_ * D_;
    int n0 = blockIdx.x * 128;

    __shared__ float As[NB][BK][128];
    __shared__ float Bs[NB][BK][128];

    int tid = threadIdx.x;
    int ty = tid >> 4, tx = tid & 15;

    int ar  = tid & 127;
    int ak8 = (tid >> 7) * 8;
    const float* arow = g_act + (size_t)(row0 + ar) * F_ + ak8;

    int bk = tid >> 4;
    int bn = (tid & 15) * 8;
    const float* wp = Wd + ((size_t)bk) * D_ + n0 + bn;

    float acc[8][8];
    #pragma unroll
    for (int i = 0; i < 8; i++)
        #pragma unroll
        for (int j = 0; j < 8; j++) acc[i][j] = 0.f;

    const int NS = F_ / BK;   // 176

    float4 ra0, ra1, rb0, rb1;
    ra0 = *(const float4*)(arow);
    ra1 = *(const float4*)(arow + 4);
    rb0 = *(const float4*)(wp);
    rb1 = *(const float4*)(wp + 4);
    {
        float a[8] = {ra0.x, ra0.y, ra0.z, ra0.w, ra1.x, ra1.y, ra1.z, ra1.w};
        #pragma unroll
        for (int q = 0; q < 8; q++) As[0][ak8 + q][ar] = a[q];
        *(float4*)&Bs[0][bk][bn]     = rb0;
        *(float4*)&Bs[0][bk][bn + 4] = rb1;
    }
    ra0 = *(const float4*)(arow + BK);
    ra1 = *(const float4*)(arow + BK + 4);
    rb0 = *(const float4*)(wp + (size_t)BK * D_);
    rb1 = *(const float4*)(wp + (size_t)BK * D_ + 4);
    __syncthreads();

    #pragma unroll 1
    for (int s = 0; s < NS; s++) {
        int cb = s % NB;
        if (s + 1 < NS) {
            int nb = (s + 1) % NB;
            float a[8] = {ra0.x, ra0.y, ra0.z, ra0.w, ra1.x, ra1.y, ra1.z, ra1.w};
            #pragma unroll
            for (int q = 0; q < 8; q++) As[nb][ak8 + q][ar] = a[q];
            *(float4*)&Bs[nb][bk][bn]     = rb0;
            *(float4*)&Bs[nb][bk][bn + 4] = rb1;
        }
        if (s + 2 < NS) {
            int k0 = (s + 2) * BK;
            ra0 = *(const float4*)(arow + k0);
            ra1 = *(const float4*)(arow + k0 + 4);
            rb0 = *(const float4*)(wp + (size_t)k0 * D_);
            rb1 = *(const float4*)(wp + (size_t)k0 * D_ + 4);
        }
        __syncthreads();
        #pragma unroll
        for (int k = 0; k < BK; k++) {
            float4 a04 = *(const float4*)&As[cb][k][8 * ty];
            float4 a48 = *(const float4*)&As[cb][k][8 * ty + 4];
            float4 b04 = *(const float4*)&Bs[cb][k][8 * tx];
            float4 b48 = *(const float4*)&Bs[cb][k][8 * tx + 4];
            float a[8] = {a04.x, a04.y, a04.z, a04.w, a48.x, a48.y, a48.z, a48.w};
            float b[8] = {b04.x, b04.y, b04.z, b04.w, b48.x, b48.y, b48.z, b48.w};
            #pragma unroll
            for (int i = 0; i < 8; i++)
                #pragma unroll
                for (int j = 0; j < 8; j++)
                    acc[i][j] += a[i] * b[j];
        }
    }

    // epilogue: scale by routing weight, deterministic y2 store
    #pragma unroll
    for (int i = 0; i < 8; i++) {
        int r = row0 + 8 * ty + i;
        float w = g_perm_w[r];
        float* yrow = g_y2 + (size_t)r * D_ + n0 + 8 * tx;
        float4 v0, v1;
        v0.x = acc[i][0] * w;  v0.y = acc[i][1] * w;
        v0.z = acc[i][2] * w;  v0.w = acc[i][3] * w;
        v1.x = acc[i][4] * w;  v1.y = acc[i][5] * w;
        v1.z = acc[i][6] * w;  v1.w = acc[i][7] * w;
        *(float4*)(yrow)     = v0;
        *(float4*)(yrow + 4) = v1;
    }
}

// ---------------- combine: out[t] = y2[slot0] + y2[slot1] ----------------
__global__ void combine_kernel(float* __restrict__ out) {
    int i = blockIdx.x * 256 + threadIdx.x;
    if (i >= OUT_ELEMS) return;
    int t = i >> 10, d = i & 1023;
    int s0 = g_tok_slot[t * 2 + 0];
    int s1 = g_tok_slot[t * 2 + 1];
    out[i] = g_y2[(size_t)s0 * D_ + d] + g_y2[(size_t)s1 * D_ + d];
}

// ---------------- launch ----------------
extern "C" void kernel_launch(void* const* d_in, const int* in_sizes, int n_in,
                              void* d_out, int out_size) {
    const float* x      = (const float*)d_in[0];
    const float* rw     = (const float*)d_in[1];
    const float* gate_w = (const float*)d_in[2];
    const float* up_w   = (const float*)d_in[3];
    const float* down_w = (const float*)d_in[4];
    float* out = (float*)d_out;

    init_kernel<<<(SLOT_PAD + 255) / 256, 256>>>();
    router_kernel<<<NTOK, 256>>>(x, rw);
    scan_kernel<<<1, 1>>>();
    fill_kernel<<<(NSLOT + 255) / 256, 256>>>();

    dim3 g1(F_ / 64, SLOT_PAD / 128);    // 44 x 136
    gemm1_kernel<<<g1, 256>>>(x, gate_w, up_w);

    dim3 g2(D_ / 128, SLOT_PAD / 128);   // 8 x 136
    gemm2_kernel<<<g2, 256>>>(down_w);

    combine_kernel<<<(OUT_ELEMS + 255) / 256, 256>>>(out);
}

// round 11
// speedup vs baseline: 3.2130x; 2.4210x over previous
#include <cuda_runtime.h>
#include <math.h>
#include <stdint.h>

// ---------------- problem constants ----------------
#define E_        8
#define NTOK      8192
#define D_        1024
#define F_        2816
#define NSLOT     (NTOK * 2)
#define SLOT_PAD  (NSLOT + E_ * 128)   // 17408
#define OUT_ELEMS (NTOK * D_)

#define BK   8                          // K per stage (one m16n8k8 step)
#define NB   3                          // triple buffer, one sync/stage
#define ROWW 136                        // padded words per k-row (bank-exact)

#define PROBE_ACT (128 * F_)
#define PROBE_Y2  (128 * D_)

// ---------------- static device scratch ----------------
__device__ __align__(128) float g_act[(size_t)SLOT_PAD * F_];
__device__ __align__(128) float g_y2[(size_t)SLOT_PAD * D_];

__device__ int   g_perm_token[SLOT_PAD];
__device__ float g_perm_w[SLOT_PAD];
__device__ int   g_tok_slot[NSLOT];
__device__ int   g_counts[E_];
__device__ int   g_cursor[E_];
__device__ int   g_pad_off[E_ + 1];
__device__ int   g_topk_idx[NSLOT];
__device__ float g_topk_w[NSLOT];
__device__ int   g_flagA;
__device__ int   g_flagB;
__device__ int   g_useMMA;

// ---------------- tf32 mma helpers ----------------
static __device__ __forceinline__ uint32_t f2tf(float v) {
    uint32_t r;
    asm("cvt.rna.tf32.f32 %0, %1;" : "=r"(r) : "f"(v));
    return r;
}
static __device__ __forceinline__ void mma_tf32(float* d, const uint32_t* a, const uint32_t* b) {
    asm volatile("mma.sync.aligned.m16n8k8.row.col.f32.tf32.tf32.f32 "
                 "{%0,%1,%2,%3}, {%4,%5,%6,%7}, {%8,%9}, {%0,%1,%2,%3};"
                 : "+f"(d[0]), "+f"(d[1]), "+f"(d[2]), "+f"(d[3])
                 : "r"(a[0]), "r"(a[1]), "r"(a[2]), "r"(a[3]), "r"(b[0]), "r"(b[1]));
}

// selftest: all-ones 16x8 @ 8x8 with k=8 -> every d element == 8.0
__global__ void mma_selftest() {
    if (threadIdx.x >= 32) return;
    uint32_t one = f2tf(1.0f);
    uint32_t a[4] = {one, one, one, one};
    uint32_t b[2] = {one, one};
    float d[4] = {0.f, 0.f, 0.f, 0.f};
    mma_tf32(d, a, b);
    bool ok = (d[0] == 8.f) && (d[1] == 8.f) && (d[2] == 8.f) && (d[3] == 8.f);
    unsigned m = __ballot_sync(0xffffffffu, ok);
    if (threadIdx.x == 0) g_useMMA = (m == 0xffffffffu) ? 1 : 0;
}

// ---------------- init ----------------
__global__ void init_kernel() {
    int i = blockIdx.x * 256 + threadIdx.x;
    if (i < SLOT_PAD) { g_perm_token[i] = -1; g_perm_w[i] = 0.0f; }
    if (i < E_) g_counts[i] = 0;
    if (i == 0) { g_flagA = 0; g_flagB = 0; }
    if (i < PROBE_ACT) g_act[i] = 0.0f;
    if (i < PROBE_Y2)  g_y2[i] = 0.0f;
}

// ---------------- router / scan / fill (proven) ----------------
__global__ void router_kernel(const float* __restrict__ x, const float* __restrict__ rw) {
    int t = blockIdx.x;
    const float* xr = x + (size_t)t * D_;
    int lane = threadIdx.x & 31;
    int w    = threadIdx.x >> 5;

    double s = 0.0;
    for (int d = lane; d < D_; d += 32)
        s += (double)xr[d] * (double)rw[d * E_ + w];
    #pragma unroll
    for (int o = 16; o > 0; o >>= 1)
        s += __shfl_down_sync(0xffffffffu, s, o);

    __shared__ double sc[E_];
    if (lane == 0) sc[w] = s;
    __syncthreads();

    if (threadIdx.x == 0) {
        double m = sc[0];
        #pragma unroll
        for (int e = 1; e < E_; e++) m = fmax(m, sc[e]);
        double p[E_], sum = 0.0;
        #pragma unroll
        for (int e = 0; e < E_; e++) { p[e] = exp(sc[e] - m); sum += p[e]; }
        #pragma unroll
        for (int e = 0; e < E_; e++) p[e] /= sum;
        int i0 = 0;
        #pragma unroll
        for (int e = 1; e < E_; e++) if (p[e] > p[i0]) i0 = e;
        int i1 = (i0 == 0) ? 1 : 0;
        #pragma unroll
        for (int e = 0; e < E_; e++) { if (e == i0) continue; if (p[e] > p[i1]) i1 = e; }
        float p0 = (float)p[i0], p1 = (float)p[i1];
        float inv = 1.0f / (p0 + p1);
        g_topk_idx[t * 2 + 0] = i0;  g_topk_idx[t * 2 + 1] = i1;
        g_topk_w[t * 2 + 0] = p0 * inv;  g_topk_w[t * 2 + 1] = p1 * inv;
        atomicAdd(&g_counts[i0], 1);
        atomicAdd(&g_counts[i1], 1);
    }
}

__global__ void scan_kernel() {
    int off = 0;
    #pragma unroll
    for (int e = 0; e < E_; e++) {
        g_pad_off[e] = off;  g_cursor[e] = off;
        off += (g_counts[e] + 127) & ~127;
    }
    g_pad_off[E_] = off;
}

__global__ void fill_kernel() {
    int idx = blockIdx.x * blockDim.x + threadIdx.x;
    if (idx >= NSLOT) return;
    int e    = g_topk_idx[idx];
    int slot = atomicAdd(&g_cursor[e], 1);
    g_perm_token[slot] = idx >> 1;
    g_perm_w[slot]     = g_topk_w[idx];
    g_tok_slot[idx]    = slot;
}

// =====================================================================
// GEMM1 (tf32 mma): act = silu(x@G) * (x@U)
// CTA 128m x 64f (gate+up). 8 warps: wm=wid>>1 (32m), wn=wid&1 (32f).
// smem per stage: As[8][136], Bs[8][136] (n 0..63 gate, 64..127 up).
// =====================================================================
__global__ __launch_bounds__(256, 2)
void gemm1_mma(const float* __restrict__ x,
               const float* __restrict__ gate_w,
               const float* __restrict__ up_w) {
    if (!g_useMMA) return;
    int row0 = blockIdx.y * 128;
    if (row0 >= g_pad_off[E_]) return;
    int e = 0;
    while (e < E_ - 1 && g_pad_off[e + 1] <= row0) e++;
    int f0  = blockIdx.x * 64;
    int tid = threadIdx.x, wid = tid >> 5, lane = tid & 31;
    int wm = wid >> 1, wn = wid & 1;

    __shared__ uint32_t As[NB][BK * ROWW];
    __shared__ uint32_t Bs[NB][BK * ROWW];

    // A loader: m = tid>>1 (0..127), kq = (tid&1)*4
    int am = tid >> 1;
    int akq = (tid & 1) * 4;
    int tok = g_perm_token[row0 + am];
    bool valid = (tok >= 0);
    const float* pa = x + (size_t)(valid ? tok : 0) * D_ + akq;

    // B loader: bk = tid>>5, n4 = (tid&31)*4
    int bk = tid >> 5;
    int bn4 = (tid & 31) * 4;
    const float* pb = (bn4 < 64)
        ? gate_w + ((size_t)e * D_ + bk) * F_ + f0 + bn4
        : up_w   + ((size_t)e * D_ + bk) * F_ + f0 + (bn4 - 64);

    float accG[2][4][4], accU[2][4][4];
    #pragma unroll
    for (int i = 0; i < 2; i++)
        #pragma unroll
        for (int j = 0; j < 4; j++)
            #pragma unroll
            for (int q = 0; q < 4; q++) { accG[i][j][q] = 0.f; accU[i][j][q] = 0.f; }

    const int NS = D_ / BK;   // 128

    float4 rA, rB;
    // prologue: stage 0 -> buf0
    rA = valid ? *(const float4*)pa : make_float4(0, 0, 0, 0);
    rB = *(const float4*)pb;
    {
        float a4[4] = {rA.x, rA.y, rA.z, rA.w};
        #pragma unroll
        for (int q = 0; q < 4; q++) As[0][(akq + q) * ROWW + am] = f2tf(a4[q]);
        uint4 bb;
        bb.x = f2tf(rB.x); bb.y = f2tf(rB.y); bb.z = f2tf(rB.z); bb.w = f2tf(rB.w);
        *(uint4*)&Bs[0][bk * ROWW + bn4] = bb;
    }
    rA = valid ? *(const float4*)(pa + BK) : make_float4(0, 0, 0, 0);
    rB = *(const float4*)(pb + (size_t)BK * F_);
    __syncthreads();

    #pragma unroll 1
    for (int s = 0; s < NS; s++) {
        int cb = s % NB;
        if (s + 1 < NS) {
            int nb = (s + 1) % NB;
            float a4[4] = {rA.x, rA.y, rA.z, rA.w};
            #pragma unroll
            for (int q = 0; q < 4; q++) As[nb][(akq + q) * ROWW + am] = f2tf(a4[q]);
            uint4 bb;
            bb.x = f2tf(rB.x); bb.y = f2tf(rB.y); bb.z = f2tf(rB.z); bb.w = f2tf(rB.w);
            *(uint4*)&Bs[nb][bk * ROWW + bn4] = bb;
        }
        if (s + 2 < NS) {
            int k0 = (s + 2) * BK;
            rA = valid ? *(const float4*)(pa + k0) : make_float4(0, 0, 0, 0);
            rB = *(const float4*)(pb + (size_t)k0 * F_);
        }
        __syncthreads();

        const uint32_t* A = As[cb];
        const uint32_t* B = Bs[cb];
        int lr = lane >> 2;          // 0..7
        int lk = lane & 3;           // 0..3
        uint32_t a[2][4];
        #pragma unroll
        for (int i = 0; i < 2; i++) {
            int m0 = 32 * wm + 16 * i + lr;
            a[i][0] = A[lk * ROWW + m0];
            a[i][1] = A[lk * ROWW + m0 + 8];
            a[i][2] = A[(lk + 4) * ROWW + m0];
            a[i][3] = A[(lk + 4) * ROWW + m0 + 8];
        }
        #pragma unroll
        for (int j = 0; j < 4; j++) {
            int ng = 32 * wn + 8 * j + lr;
            uint32_t bg[2], bu[2];
            bg[0] = B[lk * ROWW + ng];
            bg[1] = B[(lk + 4) * ROWW + ng];
            bu[0] = B[lk * ROWW + ng + 64];
            bu[1] = B[(lk + 4) * ROWW + ng + 64];
            #pragma unroll
            for (int i = 0; i < 2; i++) {
                mma_tf32(accG[i][j], a[i], bg);
                mma_tf32(accU[i][j], a[i], bu);
            }
        }
    }

    // epilogue: SwiGLU, fp32 act
    #pragma unroll
    for (int i = 0; i < 2; i++)
        #pragma unroll
        for (int j = 0; j < 4; j++) {
            int fb = f0 + 32 * wn + 8 * j + 2 * (lane & 3);
            #pragma unroll
            for (int h = 0; h < 2; h++) {
                int row = row0 + 32 * wm + 16 * i + (lane >> 2) + 8 * h;
                float g0 = accG[i][j][2 * h + 0], g1 = accG[i][j][2 * h + 1];
                float u0 = accU[i][j][2 * h + 0], u1 = accU[i][j][2 * h + 1];
                float2 o;
                o.x = (g0 / (1.0f + __expf(-g0))) * u0;
                o.y = (g1 / (1.0f + __expf(-g1))) * u1;
                *(float2*)(g_act + (size_t)row * F_ + fb) = o;
            }
        }
}

// =====================================================================
// GEMM2 (tf32 mma): y2 = w * (act @ Wdown)
// CTA 128m x 128n. 8 warps: wm=wid>>1 (32m), wn=wid&1 (64n, 8 frags).
// =====================================================================
__global__ __launch_bounds__(256, 2)
void gemm2_mma(const float* __restrict__ down_w) {
    if (!g_useMMA) return;
    int row0 = blockIdx.y * 128;
    if (row0 >= g_pad_off[E_]) return;
    int e = 0;
    while (e < E_ - 1 && g_pad_off[e + 1] <= row0) e++;
    int n0  = blockIdx.x * 128;
    int tid = threadIdx.x, wid = tid >> 5, lane = tid & 31;
    int wm = wid >> 1, wn = wid & 1;

    __shared__ uint32_t As[NB][BK * ROWW];
    __shared__ uint32_t Bs[NB][BK * ROWW];

    int am = tid >> 1;
    int akq = (tid & 1) * 4;
    const float* pa = g_act + (size_t)(row0 + am) * F_ + akq;

    int bk = tid >> 5;
    int bn4 = (tid & 31) * 4;
    const float* pb = down_w + ((size_t)e * F_ + bk) * D_ + n0 + bn4;

    float acc[2][8][4];
    #pragma unroll
    for (int i = 0; i < 2; i++)
        #pragma unroll
        for (int j = 0; j < 8; j++)
            #pragma unroll
            for (int q = 0; q < 4; q++) acc[i][j][q] = 0.f;

    const int NS = F_ / BK;   // 352

    float4 rA, rB;
    rA = *(const float4*)pa;
    rB = *(const float4*)pb;
    {
        float a4[4] = {rA.x, rA.y, rA.z, rA.w};
        #pragma unroll
        for (int q = 0; q < 4; q++) As[0][(akq + q) * ROWW + am] = f2tf(a4[q]);
        uint4 bb;
        bb.x = f2tf(rB.x); bb.y = f2tf(rB.y); bb.z = f2tf(rB.z); bb.w = f2tf(rB.w);
        *(uint4*)&Bs[0][bk * ROWW + bn4] = bb;
    }
    rA = *(const float4*)(pa + BK);
    rB = *(const float4*)(pb + (size_t)BK * D_);
    __syncthreads();

    #pragma unroll 1
    for (int s = 0; s < NS; s++) {
        int cb = s % NB;
        if (s + 1 < NS) {
            int nb = (s + 1) % NB;
            float a4[4] = {rA.x, rA.y, rA.z, rA.w};
            #pragma unroll
            for (int q = 0; q < 4; q++) As[nb][(akq + q) * ROWW + am] = f2tf(a4[q]);
            uint4 bb;
            bb.x = f2tf(rB.x); bb.y = f2tf(rB.y); bb.z = f2tf(rB.z); bb.w = f2tf(rB.w);
            *(uint4*)&Bs[nb][bk * ROWW + bn4] = bb;
        }
        if (s + 2 < NS) {
            int k0 = (s + 2) * BK;
            rA = *(const float4*)(pa + k0);
            rB = *(const float4*)(pb + (size_t)k0 * D_);
        }
        __syncthreads();

        const uint32_t* A = As[cb];
        const uint32_t* B = Bs[cb];
        int lr = lane >> 2;
        int lk = lane & 3;
        uint32_t a[2][4];
        #pragma unroll
        for (int i = 0; i < 2; i++) {
            int m0 = 32 * wm + 16 * i + lr;
            a[i][0] = A[lk * ROWW + m0];
            a[i][1] = A[lk * ROWW + m0 + 8];
            a[i][2] = A[(lk + 4) * ROWW + m0];
            a[i][3] = A[(lk + 4) * ROWW + m0 + 8];
        }
        #pragma unroll
        for (int j = 0; j < 8; j++) {
            int nn = 64 * wn + 8 * j + lr;
            uint32_t b[2];
            b[0] = B[lk * ROWW + nn];
            b[1] = B[(lk + 4) * ROWW + nn];
            #pragma unroll
            for (int i = 0; i < 2; i++)
                mma_tf32(acc[i][j], a[i], b);
        }
    }

    // epilogue
    #pragma unroll
    for (int i = 0; i < 2; i++)
        #pragma unroll
        for (int h = 0; h < 2; h++) {
            int row = row0 + 32 * wm + 16 * i + (lane >> 2) + 8 * h;
            float w = g_perm_w[row];
            #pragma unroll
            for (int j = 0; j < 8; j++) {
                int nn = n0 + 64 * wn + 8 * j + 2 * (lane & 3);
                float2 v;
                v.x = acc[i][j][2 * h + 0] * w;
                v.y = acc[i][j][2 * h + 1] * w;
                *(float2*)(g_y2 + (size_t)row * D_ + nn) = v;
            }
        }
}

// ---------------- probes ----------------
__global__ void probeA_kernel() {
    int i = blockIdx.x * 256 + threadIdx.x;
    if (i >= PROBE_ACT) return;
    if (((const uint32_t*)g_act)[i] != 0) g_flagA = 1;
}
__global__ void probeB_kernel() {
    int i = blockIdx.x * 256 + threadIdx.x;
    if (i >= PROBE_Y2) return;
    if (((const uint32_t*)g_y2)[i] != 0) g_flagB = 1;
}

// ---------------- SIMT fallbacks (fp32; skip when mma worked) ----------
#define SBM 64
#define SBN 64
#define SBK 16

__global__ __launch_bounds__(256)
void gemm1_simt(const float* __restrict__ x,
                const float* __restrict__ gate_w,
                const float* __restrict__ up_w) {
    if (g_flagA) return;
    int row0 = blockIdx.y * SBM;
    if (row0 >= g_pad_off[E_]) return;
    int e = 0;
    while (e < E_ - 1 && g_pad_off[e + 1] <= row0) e++;
    const float* G = gate_w + (size_t)e * D_ * F_;
    const float* U = up_w   + (size_t)e * D_ * F_;
    int n0 = blockIdx.x * SBN;

    __shared__ float As2[SBK][SBM + 4];
    __shared__ float Bg[SBK][SBN];
    __shared__ float Bu[SBK][SBN];

    int tid   = threadIdx.x;
    int a_row = tid >> 2;
    int a_k   = (tid & 3) * 4;
    int tok   = g_perm_token[row0 + a_row];
    bool valid = (tok >= 0);
    const float* xrow = x + (size_t)(valid ? tok : 0) * D_;

    int b_k = tid >> 4;
    int b_n = (tid & 15) * 4;
    int ty = tid >> 4, tx = tid & 15;

    float ag[4][4] = {}, au[4][4] = {};

    for (int k0 = 0; k0 < D_; k0 += SBK) {
        float4 av = valid ? *(const float4*)(xrow + k0 + a_k)
                          : make_float4(0.f, 0.f, 0.f, 0.f);
        As2[a_k + 0][a_row] = av.x;  As2[a_k + 1][a_row] = av.y;
        As2[a_k + 2][a_row] = av.z;  As2[a_k + 3][a_row] = av.w;
        *(float4*)&Bg[b_k][b_n] = *(const float4*)(G + (size_t)(k0 + b_k) * F_ + n0 + b_n);
        *(float4*)&Bu[b_k][b_n] = *(const float4*)(U + (size_t)(k0 + b_k) * F_ + n0 + b_n);
        __syncthreads();
        #pragma unroll
        for (int kk = 0; kk < SBK; kk++) {
            float4 a4 = *(const float4*)&As2[kk][ty * 4];
            float4 g4 = *(const float4*)&Bg[kk][tx * 4];
            float4 u4 = *(const float4*)&Bu[kk][tx * 4];
            float am[4] = {a4.x, a4.y, a4.z, a4.w};
            float gm[4] = {g4.x, g4.y, g4.z, g4.w};
            float um[4] = {u4.x, u4.y, u4.z, u4.w};
            #pragma unroll
            for (int i = 0; i < 4; i++)
                #pragma unroll
                for (int j = 0; j < 4; j++) {
                    ag[i][j] += am[i] * gm[j];
                    au[i][j] += am[i] * um[j];
                }
        }
        __syncthreads();
    }

    #pragma unroll
    for (int i = 0; i < 4; i++) {
        int r = row0 + ty * 4 + i;
        size_t base = (size_t)r * F_ + n0 + tx * 4;
        #pragma unroll
        for (int j = 0; j < 4; j++) {
            float g = ag[i][j], u = au[i][j];
            g_act[base + j] = (g / (1.0f + __expf(-g))) * u;
        }
    }
}

__global__ __launch_bounds__(256)
void gemm2_simt(const float* __restrict__ down_w) {
    if (g_flagB) return;
    int row0 = blockIdx.y * SBM;
    if (row0 >= g_pad_off[E_]) return;
    int e = 0;
    while (e < E_ - 1 && g_pad_off[e + 1] <= row0) e++;
    const float* Wd = down_w + (size_t)e * F_ * D_;
    int n0 = blockIdx.x * SBN;

    __shared__ float As2[SBK][SBM + 4];
    __shared__ float Bs2[SBK][SBN];

    int tid   = threadIdx.x;
    int a_row = tid >> 2;
    int a_k   = (tid & 3) * 4;
    size_t abase = (size_t)(row0 + a_row) * F_;

    int b_k = tid >> 4;
    int b_n = (tid & 15) * 4;
    int ty = tid >> 4, tx = tid & 15;

    float acc[4][4] = {};

    for (int k0 = 0; k0 < F_; k0 += SBK) {
        float4 av = *(const float4*)(g_act + abase + k0 + a_k);
        As2[a_k + 0][a_row] = av.x;  As2[a_k + 1][a_row] = av.y;
        As2[a_k + 2][a_row] = av.z;  As2[a_k + 3][a_row] = av.w;
        *(float4*)&Bs2[b_k][b_n] = *(const float4*)(Wd + (size_t)(k0 + b_k) * D_ + n0 + b_n);
        __syncthreads();
        #pragma unroll
        for (int kk = 0; kk < SBK; kk++) {
            float4 a4 = *(const float4*)&As2[kk][ty * 4];
            float4 b4 = *(const float4*)&Bs2[kk][tx * 4];
            float am[4] = {a4.x, a4.y, a4.z, a4.w};
            float bm[4] = {b4.x, b4.y, b4.z, b4.w};
            #pragma unroll
            for (int i = 0; i < 4; i++)
                #pragma unroll
                for (int j = 0; j < 4; j++)
                    acc[i][j] += am[i] * bm[j];
        }
        __syncthreads();
    }

    #pragma unroll
    for (int i = 0; i < 4; i++) {
        int r = row0 + ty * 4 + i;
        float w = g_perm_w[r];
        float* yrow = g_y2 + (size_t)r * D_ + n0 + tx * 4;
        #pragma unroll
        for (int j = 0; j < 4; j++)
            yrow[j] = acc[i][j] * w;
    }
}

// ---------------- combine ----------------
__global__ void combine_kernel(float* __restrict__ out) {
    int i = blockIdx.x * 256 + threadIdx.x;
    if (i >= OUT_ELEMS) return;
    int t = i >> 10, d = i & 1023;
    int s0 = g_tok_slot[t * 2 + 0];
    int s1 = g_tok_slot[t * 2 + 1];
    out[i] = g_y2[(size_t)s0 * D_ + d] + g_y2[(size_t)s1 * D_ + d];
}

// ---------------- launch ----------------
extern "C" void kernel_launch(void* const* d_in, const int* in_sizes, int n_in,
                              void* d_out, int out_size) {
    const float* x      = (const float*)d_in[0];
    const float* rw     = (const float*)d_in[1];
    const float* gate_w = (const float*)d_in[2];
    const float* up_w   = (const float*)d_in[3];
    const float* down_w = (const float*)d_in[4];
    float* out = (float*)d_out;

    mma_selftest<<<1, 32>>>();
    init_kernel<<<(PROBE_ACT + 255) / 256, 256>>>();
    router_kernel<<<NTOK, 256>>>(x, rw);
    scan_kernel<<<1, 1>>>();
    fill_kernel<<<(NSLOT + 255) / 256, 256>>>();

    dim3 g1m(F_ / 64, SLOT_PAD / 128);   // 44 x 136
    gemm1_mma<<<g1m, 256>>>(x, gate_w, up_w);
    probeA_kernel<<<(PROBE_ACT + 255) / 256, 256>>>();
    dim3 g1s(F_ / SBN, SLOT_PAD / SBM);
    gemm1_simt<<<g1s, 256>>>(x, gate_w, up_w);

    dim3 g2m(D_ / 128, SLOT_PAD / 128);  // 8 x 136
    gemm2_mma<<<g2m, 256>>>(down_w);
    probeB_kernel<<<(PROBE_Y2 + 255) / 256, 256>>>();
    dim3 g2s(D_ / SBN, SLOT_PAD / SBM);
    gemm2_simt<<<g2s, 256>>>(down_w);

    combine_kernel<<<(OUT_ELEMS + 255) / 256, 256>>>(out);
}